// round 7
// baseline (speedup 1.0000x reference)
#include <cuda_runtime.h>
#include <cuda_fp16.h>
#include <cstdint>

// ---------------- problem constants ----------------
#define L_T   16
#define BSZ   8
#define H_    32
#define W_    32
#define U_    128
#define P_    256
#define FRAMES 128
#define SP    (BSZ*H_*W_*P_)      // 2,097,152
#define YS_N  (L_T*BSZ*H_*W_*U_)  // 16,777,216
#define BUS_N (L_T*BSZ*H_*W_*P_)  // 33,554,432
#define U_N   (L_T*BSZ*H_*W_*U_)  // 16,777,216
#define EPS_GN 1e-5f

#define NB_W  589824   // half: [chunk18][nb4][wn4][nt4][ks4][lane32][reg2][h2]
#define NC_W  589824   // half: [chunk72][wn4][nt4][ks4][lane32][reg2][h2]

#define SMEM_GEMM 147456   // 3 stages x (32KB A + 16KB W)

// ---------------- device scratch (allocation-free) ----------------
__device__ __align__(16) __half g_WBh[NB_W];
__device__ __align__(16) __half g_WCh[NC_W];
__device__ float g_Are[P_];
__device__ float g_Aim[P_];
__device__ __align__(16) __half g_u_h[U_N];
__device__ __align__(16) __half2 g_Bus_hre[BUS_N / 2];
__device__ __align__(16) __half2 g_Bus_him[BUS_N / 2];
__device__ __align__(16) __half g_xh_re[BUS_N];
__device__ __align__(16) __half g_xh_im[BUS_N];
__device__ __align__(16) float g_ys[YS_N];

#define LDMX4(r0, r1, r2, r3, addr) \
    asm volatile("ldmatrix.sync.aligned.m8n8.x4.shared.b16 {%0,%1,%2,%3}, [%4];" \
                 : "=r"(r0), "=r"(r1), "=r"(r2), "=r"(r3) : "r"(addr))

#define MMAH(c, a0, a1, a2, a3, b) asm volatile( \
    "mma.sync.aligned.m16n8k16.row.col.f32.f16.f16.f32 " \
    "{%0,%1,%2,%3},{%4,%5,%6,%7},{%8,%9},{%0,%1,%2,%3};" \
    : "+f"((c)[0]), "+f"((c)[1]), "+f"((c)[2]), "+f"((c)[3]) \
    : "r"(a0), "r"(a1), "r"(a2), "r"(a3), "r"((b).x), "r"((b).y))

#define CP16(dst, src, pred) do { \
    int _sz = (pred) ? 16 : 0; \
    asm volatile("cp.async.cg.shared.global [%0], [%1], 16, %2;" \
                 :: "r"(dst), "l"(src), "r"(_sz)); \
} while (0)

#define CP_COMMIT() asm volatile("cp.async.commit_group;" ::: "memory")
#define CP_WAIT2()  asm volatile("cp.async.wait_group 2;" ::: "memory")
#define CP_WAIT0()  asm volatile("cp.async.wait_group 0;" ::: "memory")

// ---------------- K0: discretization + weight fragment pre-permute (half) --
__global__ void k_pre(const float* __restrict__ Lre, const float* __restrict__ Lim,
                      const float* __restrict__ lstep,
                      const float* __restrict__ B_ri, const float* __restrict__ C_ri) {
    int tid = blockIdx.x * blockDim.x + threadIdx.x;
    if (tid < P_) {
        float st = expf(lstep[tid]);
        g_Are[tid] = fminf(Lre[tid], -1e-4f) * st;
        g_Aim[tid] = Lim[tid] * st;
    }
    if (tid < NB_W) {
        int h = tid & 1, reg = (tid >> 1) & 1, lane = (tid >> 2) & 31;
        int ks = (tid >> 7) & 3, nt = (tid >> 9) & 3, wn = (tid >> 11) & 3;
        int nb = (tid >> 13) & 3, chunk = tid >> 15;            // 0..17
        int kch = ks * 16 + reg * 8 + (lane & 3) * 2 + h;
        int tap = chunk >> 1, cb = chunk & 1;
        int c = cb * 64 + kch;
        int n = nb * 128 + wn * 32 + nt * 8 + (lane >> 2);
        int plane = n >> 8, p = n & 255;
        float v = B_ri[(((size_t)p * 128 + c) * 9 + tap) * 2 + plane] * expf(lstep[p]);
        g_WBh[tid] = __float2half_rn(v);
    }
    int t2 = tid - NB_W;
    if (t2 >= 0 && t2 < NC_W) {
        int h = t2 & 1, reg = (t2 >> 1) & 1, lane = (t2 >> 2) & 31;
        int ks = (t2 >> 7) & 3, nt = (t2 >> 9) & 3, wn = (t2 >> 11) & 3;
        int chunk = t2 >> 13;                                   // 0..71
        int kch = ks * 16 + reg * 8 + (lane & 3) * 2 + h;
        int tap = chunk >> 3, kc8 = chunk & 7;
        int cidx = kc8 * 64 + kch;
        int u = wn * 32 + nt * 8 + (lane >> 2);
        float v;
        if (cidx < 256) v =  2.f * C_ri[(((size_t)u * 256 + cidx) * 9 + tap) * 2];
        else            v = -2.f * C_ri[(((size_t)u * 256 + (cidx - 256)) * 9 + tap) * 2 + 1];
        g_WCh[t2] = __float2half_rn(v);
    }
}

// ---------------- K0b: input f32 -> half -----------------------------------
__global__ void k_uh(const float* __restrict__ u_in) {
    int i = blockIdx.x * blockDim.x + threadIdx.x;   // groups of 4 floats
    float4 v = ((const float4*)u_in)[i];
    __half2* dst = (__half2*)g_u_h;
    dst[2 * i]     = __floats2half2_rn(v.x, v.y);
    dst[2 * i + 1] = __floats2half2_rn(v.z, v.w);
}

// ---------------- shared GEMM compute macro (fp16, BK=64) ------------------
#define COMP(s) do { \
    uint32_t ab = abase + (s) * 32768; \
    uint32_t wb = wbase + (s) * 16384; \
    _Pragma("unroll") \
    for (int ks = 0; ks < 4; ks++) { \
        uint2 b[4]; \
        _Pragma("unroll") \
        for (int nt = 0; nt < 4; nt++) { \
            uint32_t waddr = wb + ((((wn * 4 + nt) * 4 + ks) * 32 + lane) << 3); \
            asm volatile("ld.shared.v2.b32 {%0,%1}, [%2];" \
                         : "=r"(b[nt].x), "=r"(b[nt].y) : "r"(waddr)); \
        } \
        _Pragma("unroll") \
        for (int mt = 0; mt < 4; mt++) { \
            uint32_t a0, a1, a2, a3; \
            uint32_t ad = ab + (wm * 64 + mt * 16 + lrow) * 128 + \
                          ((ks * 32 + lcol) ^ ((lrow & 7) << 4)); \
            LDMX4(a0, a1, a2, a3, ad); \
            _Pragma("unroll") \
            for (int nt = 0; nt < 4; nt++) MMAH(acc[mt][nt], a0, a1, a2, a3, b[nt]); \
        } \
    } \
} while (0)

// ---------------- GEMM B: Bus(re|im) = u (*) B_bar  (half output) ----------
// grid (nb4, slab4, f128), 512 thr. BM=256 px, BN=128, BK=64, 18 chunks.
__global__ __launch_bounds__(512, 1) void k_gemmB(int dummy) {
    extern __shared__ __align__(16) char smem[];
    int tid = threadIdx.x, lane = tid & 31, wid = tid >> 5;
    int wm = wid >> 2, wn = wid & 3;
    int g8 = lane >> 2, tig = lane & 3;
    int lrow = lane & 15, lcol = lane & 16;
    int nb = blockIdx.x, slab = blockIdx.y, f = blockIdx.z;
    int y0 = slab * 8;
    uint32_t abase = (uint32_t)__cvta_generic_to_shared(smem);
    uint32_t wbase = abase + 98304;

    float acc[4][4][4];
#pragma unroll
    for (int i = 0; i < 4; i++)
#pragma unroll
        for (int j = 0; j < 4; j++)
#pragma unroll
            for (int e = 0; e < 4; e++) acc[i][j][e] = 0.f;

#define ISSUE_B(s, k) do { \
    int tap = (k) >> 1, cb = (k) & 1; \
    int ky = tap / 3 - 1, kx = tap % 3 - 1; \
    _Pragma("unroll") \
    for (int q = 0; q < 4; q++) { \
        int idx = q * 512 + tid, m = idx >> 3, c8 = idx & 7; \
        int yy = y0 + (m >> 5) + ky, xx = (m & 31) + kx; \
        bool ok = ((unsigned)yy < 32u) && ((unsigned)xx < 32u); \
        const __half* src = g_u_h + ((((size_t)f * 32 + yy) * 32 + xx) << 7) + cb * 64 + c8 * 8; \
        uint32_t dst = abase + (s) * 32768 + m * 128 + ((c8 * 16) ^ ((m & 7) << 4)); \
        CP16(dst, src, ok); \
    } \
    const __half* wsrc = g_WBh + (((size_t)(k) * 4 + nb) << 13); \
    _Pragma("unroll") \
    for (int q = 0; q < 2; q++) { \
        int idx = q * 512 + tid; \
        CP16(wbase + (s) * 16384 + idx * 16, wsrc + idx * 8, true); \
    } \
} while (0)

    ISSUE_B(0, 0); CP_COMMIT();
    ISSUE_B(1, 1); CP_COMMIT();
    for (int k = 0; k < 18; k++) {
        int s = k % 3;
        if (k + 2 < 18) { ISSUE_B((k + 2) % 3, k + 2); CP_COMMIT(); CP_WAIT2(); }
        else CP_WAIT0();
        __syncthreads();
        COMP(s);
        __syncthreads();
    }

    __half* base = (nb < 2) ? (__half*)g_Bus_hre : (__half*)g_Bus_him;
    int ch0 = (nb & 1) * 128 + wn * 32;
#pragma unroll
    for (int mt = 0; mt < 4; mt++) {
        int m1 = wm * 64 + mt * 16 + g8, m2 = m1 + 8;
        size_t pix1 = (((size_t)f * 32 + y0 + (m1 >> 5)) * 32 + (m1 & 31)) * 256;
        size_t pix2 = (((size_t)f * 32 + y0 + (m2 >> 5)) * 32 + (m2 & 31)) * 256;
#pragma unroll
        for (int nt = 0; nt < 4; nt++) {
            int ch = ch0 + nt * 8 + tig * 2;
            *(__half2*)(base + pix1 + ch) = __floats2half2_rn(acc[mt][nt][0], acc[mt][nt][1]);
            *(__half2*)(base + pix2 + ch) = __floats2half2_rn(acc[mt][nt][2], acc[mt][nt][3]);
        }
    }
    (void)dummy;
}

// ---------------- K2: scan (half2 Bus in, half xs out, f32 x_last) ---------
__global__ __launch_bounds__(256) void k_scan(const float* __restrict__ x0,
                                              float* __restrict__ out) {
    int t = blockIdx.x * 256 + threadIdx.x;          // half2 index < SP/2
    int p0 = (2 * t) & 255;
    float ar0 = g_Are[p0],     ai0 = g_Aim[p0];
    float ar1 = g_Are[p0 + 1], ai1 = g_Aim[p0 + 1];
    float2 xv = ((const float2*)x0)[t];
    float xr0 = xv.x, xi0 = 0.f, xr1 = xv.y, xi1 = 0.f;
    size_t idx = (size_t)t;
#pragma unroll
    for (int l = 0; l < L_T; l++, idx += SP / 2) {
        float2 br = __half22float2(g_Bus_hre[idx]);
        float2 bi = __half22float2(g_Bus_him[idx]);
        float nr0 = fmaf(ar0, xr0, fmaf(-ai0, xi0, br.x));
        float ni0 = fmaf(ar0, xi0, fmaf( ai0, xr0, bi.x));
        float nr1 = fmaf(ar1, xr1, fmaf(-ai1, xi1, br.y));
        float ni1 = fmaf(ar1, xi1, fmaf( ai1, xr1, bi.y));
        xr0 = nr0; xi0 = ni0; xr1 = nr1; xi1 = ni1;
        ((__half2*)g_xh_re)[idx] = __floats2half2_rn(xr0, xr1);
        ((__half2*)g_xh_im)[idx] = __floats2half2_rn(xi0, xi1);
    }
    ((float4*)out)[t] = make_float4(xr0, xi0, xr1, xi1);
}

// ---------------- GEMM C: ys = 2Re(C (*) x) --------------------------------
// grid (slab4, f128), 512 thr. BM=256, BN=128, BK=64, 72 chunks.
__global__ __launch_bounds__(512, 1) void k_gemmC(int dummy) {
    extern __shared__ __align__(16) char smem[];
    int tid = threadIdx.x, lane = tid & 31, wid = tid >> 5;
    int wm = wid >> 2, wn = wid & 3;
    int g8 = lane >> 2, tig = lane & 3;
    int lrow = lane & 15, lcol = lane & 16;
    int slab = blockIdx.x, f = blockIdx.y;
    int y0 = slab * 8;
    uint32_t abase = (uint32_t)__cvta_generic_to_shared(smem);
    uint32_t wbase = abase + 98304;

    float acc[4][4][4];
#pragma unroll
    for (int i = 0; i < 4; i++)
#pragma unroll
        for (int j = 0; j < 4; j++)
#pragma unroll
            for (int e = 0; e < 4; e++) acc[i][j][e] = 0.f;

#define ISSUE_C(s, k) do { \
    int tap = (k) >> 3, kc8 = (k) & 7; \
    const __half* srcb = (kc8 < 4) ? g_xh_re : g_xh_im; \
    int c0 = (kc8 & 3) * 64; \
    int ky = tap / 3 - 1, kx = tap % 3 - 1; \
    _Pragma("unroll") \
    for (int q = 0; q < 4; q++) { \
        int idx = q * 512 + tid, m = idx >> 3, c8 = idx & 7; \
        int yy = y0 + (m >> 5) + ky, xx = (m & 31) + kx; \
        bool ok = ((unsigned)yy < 32u) && ((unsigned)xx < 32u); \
        const __half* src = srcb + ((((size_t)f * 32 + yy) * 32 + xx) << 8) + c0 + c8 * 8; \
        uint32_t dst = abase + (s) * 32768 + m * 128 + ((c8 * 16) ^ ((m & 7) << 4)); \
        CP16(dst, src, ok); \
    } \
    const __half* wsrc = g_WCh + ((size_t)(k) << 13); \
    _Pragma("unroll") \
    for (int q = 0; q < 2; q++) { \
        int idx = q * 512 + tid; \
        CP16(wbase + (s) * 16384 + idx * 16, wsrc + idx * 8, true); \
    } \
} while (0)

    ISSUE_C(0, 0); CP_COMMIT();
    ISSUE_C(1, 1); CP_COMMIT();
    for (int k = 0; k < 72; k++) {
        int s = k % 3;
        if (k + 2 < 72) { ISSUE_C((k + 2) % 3, k + 2); CP_COMMIT(); CP_WAIT2(); }
        else CP_WAIT0();
        __syncthreads();
        COMP(s);
        __syncthreads();
    }

#pragma unroll
    for (int mt = 0; mt < 4; mt++) {
        int m1 = wm * 64 + mt * 16 + g8, m2 = m1 + 8;
        size_t pix1 = (((size_t)f * 32 + y0 + (m1 >> 5)) * 32 + (m1 & 31)) * 128;
        size_t pix2 = (((size_t)f * 32 + y0 + (m2 >> 5)) * 32 + (m2 & 31)) * 128;
#pragma unroll
        for (int nt = 0; nt < 4; nt++) {
            int ch = wn * 32 + nt * 8 + tig * 2;
            *(float2*)(g_ys + pix1 + ch) = make_float2(acc[mt][nt][0], acc[mt][nt][1]);
            *(float2*)(g_ys + pix2 + ch) = make_float2(acc[mt][nt][2], acc[mt][nt][3]);
        }
    }
    (void)dummy;
}

// ---------------- K4: fused depthwise-D + GroupNorm(32) + GELU -------------
__global__ __launch_bounds__(256) void k_gn(const float* __restrict__ u_in,
                                            const float* __restrict__ Dk,
                                            const float* __restrict__ scale,
                                            const float* __restrict__ bias,
                                            float* __restrict__ out) {
    int f = blockIdx.x, g = blockIdx.y;
    int tid = threadIdx.x;
    int cl = tid & 3, ch = g * 4 + cl;
    size_t fbase = (size_t)f * (H_ * W_ * U_);

    float dk[9];
#pragma unroll
    for (int j = 0; j < 9; j++) dk[j] = Dk[j * U_ + ch];
    float sc = scale[ch], bi = bias[ch];

    float v[16];
    float s = 0.f, s2 = 0.f;
#pragma unroll
    for (int it = 0; it < 16; it++) {
        int yx = it * 64 + (tid >> 2);
        int y = yx >> 5, x = yx & 31;
        size_t idx = fbase + (size_t)yx * U_ + ch;
        float val = g_ys[idx];
        const float* up = u_in + idx;
#pragma unroll
        for (int dy = -1; dy <= 1; dy++)
#pragma unroll
            for (int dx = -1; dx <= 1; dx++) {
                int yy = y + dy, xx = x + dx;
                if ((unsigned)yy < 32u && (unsigned)xx < 32u)
                    val = fmaf(up[(dy * 32 + dx) * 128], dk[(dy + 1) * 3 + (dx + 1)], val);
            }
        v[it] = val;
        s += val; s2 += val * val;
    }

    __shared__ float rs[8], rs2[8];
    unsigned m = 0xffffffffu;
#pragma unroll
    for (int o = 16; o > 0; o >>= 1) {
        s  += __shfl_down_sync(m, s, o);
        s2 += __shfl_down_sync(m, s2, o);
    }
    if ((tid & 31) == 0) { rs[tid >> 5] = s; rs2[tid >> 5] = s2; }
    __syncthreads();
    if (tid == 0) {
        float ts = 0.f, ts2 = 0.f;
#pragma unroll
        for (int i = 0; i < 8; i++) { ts += rs[i]; ts2 += rs2[i]; }
        float mu  = ts * (1.f / 4096.f);
        float var = ts2 * (1.f / 4096.f) - mu * mu;
        rs[0]  = mu;
        rs2[0] = rsqrtf(var + EPS_GN);
    }
    __syncthreads();
    float mu = rs[0], rstd = rs2[0];

    float* outy = out + (size_t)SP * 2;
#pragma unroll
    for (int it = 0; it < 16; it++) {
        int yx = it * 64 + (tid >> 2);
        size_t idx = fbase + (size_t)yx * U_ + ch;
        float h = (v[it] - mu) * rstd * sc + bi;
        float t = 0.7978845608028654f * (h + 0.044715f * h * h * h);
        outy[idx] = 0.5f * h * (1.f + tanhf(t));
    }
}

// ---------------- launch ----------------
extern "C" void kernel_launch(void* const* d_in, const int* in_sizes, int n_in,
                              void* d_out, int out_size) {
    const float* u_in  = (const float*)d_in[0];
    const float* x0    = (const float*)d_in[1];
    const float* Lre   = (const float*)d_in[2];
    const float* Lim   = (const float*)d_in[3];
    const float* B_ri  = (const float*)d_in[4];
    const float* C_ri  = (const float*)d_in[5];
    const float* lstep = (const float*)d_in[6];
    const float* Dk    = (const float*)d_in[7];
    const float* gsc   = (const float*)d_in[8];
    const float* gbi   = (const float*)d_in[9];
    float* out = (float*)d_out;
    (void)in_sizes; (void)n_in; (void)out_size;

    cudaFuncSetAttribute(k_gemmB, cudaFuncAttributeMaxDynamicSharedMemorySize, SMEM_GEMM);
    cudaFuncSetAttribute(k_gemmC, cudaFuncAttributeMaxDynamicSharedMemorySize, SMEM_GEMM);

    k_pre<<<(NB_W + NC_W + 255) / 256, 256>>>(Lre, Lim, lstep, B_ri, C_ri);
    k_uh<<<U_N / 4 / 256, 256>>>(u_in);
    k_gemmB<<<dim3(4, 4, FRAMES), 512, SMEM_GEMM>>>(0);
    k_scan<<<SP / 2 / 256, 256>>>(x0, out);
    k_gemmC<<<dim3(4, FRAMES), 512, SMEM_GEMM>>>(0);
    k_gn<<<dim3(FRAMES, 32), 256>>>(u_in, Dk, gsc, gbi, out);
}

// round 8
// speedup vs baseline: 1.0585x; 1.0585x over previous
#include <cuda_runtime.h>
#include <cuda_fp16.h>
#include <cstdint>

// ---------------- problem constants ----------------
#define L_T   16
#define BSZ   8
#define H_    32
#define W_    32
#define U_    128
#define P_    256
#define FRAMES 128
#define SP    (BSZ*H_*W_*P_)      // 2,097,152
#define YS_N  (L_T*BSZ*H_*W_*U_)  // 16,777,216
#define BUS_N (L_T*BSZ*H_*W_*P_)  // 33,554,432
#define U_N   (L_T*BSZ*H_*W_*U_)  // 16,777,216
#define EPS_GN 1e-5f

#define NB_W  589824   // half: [chunk18][nb4][wn4][nt4][ks4][lane32][reg2][h2]
#define NC_W  589824   // half: [chunk72][wn4][nt4][ks4][lane32][reg2][h2]

#define SMEM_GEMM 147456   // 3 stages x (32KB A + 16KB W)

// ---------------- device scratch (allocation-free) ----------------
__device__ __align__(16) __half g_WBh[NB_W];
__device__ __align__(16) __half g_WCh[NC_W];
__device__ float g_Are[P_];
__device__ float g_Aim[P_];
__device__ __align__(16) __half g_u_h[U_N];
__device__ __align__(16) __half2 g_Bus_hre[BUS_N / 2];
__device__ __align__(16) __half2 g_Bus_him[BUS_N / 2];
__device__ __align__(16) __half g_xh_re[BUS_N];
__device__ __align__(16) __half g_xh_im[BUS_N];
__device__ __align__(16) float g_ys[YS_N];

#define LDMX4(r0, r1, r2, r3, addr) \
    asm volatile("ldmatrix.sync.aligned.m8n8.x4.shared.b16 {%0,%1,%2,%3}, [%4];" \
                 : "=r"(r0), "=r"(r1), "=r"(r2), "=r"(r3) : "r"(addr))

#define MMAH(c, a0, a1, a2, a3, b) asm volatile( \
    "mma.sync.aligned.m16n8k16.row.col.f32.f16.f16.f32 " \
    "{%0,%1,%2,%3},{%4,%5,%6,%7},{%8,%9},{%0,%1,%2,%3};" \
    : "+f"((c)[0]), "+f"((c)[1]), "+f"((c)[2]), "+f"((c)[3]) \
    : "r"(a0), "r"(a1), "r"(a2), "r"(a3), "r"((b).x), "r"((b).y))

#define CP16(dst, src, pred) do { \
    int _sz = (pred) ? 16 : 0; \
    asm volatile("cp.async.cg.shared.global [%0], [%1], 16, %2;" \
                 :: "r"(dst), "l"(src), "r"(_sz)); \
} while (0)

#define CP_COMMIT() asm volatile("cp.async.commit_group;" ::: "memory")
#define CP_WAIT1()  asm volatile("cp.async.wait_group 1;" ::: "memory")
#define CP_WAIT0()  asm volatile("cp.async.wait_group 0;" ::: "memory")

// ---------------- K0: discretization + weight fragment pre-permute (half) --
__global__ void k_pre(const float* __restrict__ Lre, const float* __restrict__ Lim,
                      const float* __restrict__ lstep,
                      const float* __restrict__ B_ri, const float* __restrict__ C_ri) {
    int tid = blockIdx.x * blockDim.x + threadIdx.x;
    if (tid < P_) {
        float st = expf(lstep[tid]);
        g_Are[tid] = fminf(Lre[tid], -1e-4f) * st;
        g_Aim[tid] = Lim[tid] * st;
    }
    if (tid < NB_W) {
        int h = tid & 1, reg = (tid >> 1) & 1, lane = (tid >> 2) & 31;
        int ks = (tid >> 7) & 3, nt = (tid >> 9) & 3, wn = (tid >> 11) & 3;
        int nb = (tid >> 13) & 3, chunk = tid >> 15;            // 0..17
        int kch = ks * 16 + reg * 8 + (lane & 3) * 2 + h;
        int tap = chunk >> 1, cb = chunk & 1;
        int c = cb * 64 + kch;
        int n = nb * 128 + wn * 32 + nt * 8 + (lane >> 2);
        int plane = n >> 8, p = n & 255;
        float v = B_ri[(((size_t)p * 128 + c) * 9 + tap) * 2 + plane] * expf(lstep[p]);
        g_WBh[tid] = __float2half_rn(v);
    }
    int t2 = tid - NB_W;
    if (t2 >= 0 && t2 < NC_W) {
        int h = t2 & 1, reg = (t2 >> 1) & 1, lane = (t2 >> 2) & 31;
        int ks = (t2 >> 7) & 3, nt = (t2 >> 9) & 3, wn = (t2 >> 11) & 3;
        int chunk = t2 >> 13;                                   // 0..71
        int kch = ks * 16 + reg * 8 + (lane & 3) * 2 + h;
        int tap = chunk >> 3, kc8 = chunk & 7;
        int cidx = kc8 * 64 + kch;
        int u = wn * 32 + nt * 8 + (lane >> 2);
        float v;
        if (cidx < 256) v =  2.f * C_ri[(((size_t)u * 256 + cidx) * 9 + tap) * 2];
        else            v = -2.f * C_ri[(((size_t)u * 256 + (cidx - 256)) * 9 + tap) * 2 + 1];
        g_WCh[t2] = __float2half_rn(v);
    }
}

// ---------------- K0b: input f32 -> half -----------------------------------
__global__ void k_uh(const float* __restrict__ u_in) {
    int i = blockIdx.x * blockDim.x + threadIdx.x;   // groups of 4 floats
    float4 v = ((const float4*)u_in)[i];
    __half2* dst = (__half2*)g_u_h;
    dst[2 * i]     = __floats2half2_rn(v.x, v.y);
    dst[2 * i + 1] = __floats2half2_rn(v.z, v.w);
}

// ---------------- shared GEMM compute macro (fp16, BK=64) ------------------
#define COMP(s) do { \
    uint32_t ab = abase + (s) * 32768; \
    uint32_t wb = wbase + (s) * 16384; \
    _Pragma("unroll") \
    for (int ks = 0; ks < 4; ks++) { \
        uint2 b[4]; \
        _Pragma("unroll") \
        for (int nt = 0; nt < 4; nt++) { \
            uint32_t waddr = wb + ((((wn * 4 + nt) * 4 + ks) * 32 + lane) << 3); \
            asm volatile("ld.shared.v2.b32 {%0,%1}, [%2];" \
                         : "=r"(b[nt].x), "=r"(b[nt].y) : "r"(waddr)); \
        } \
        _Pragma("unroll") \
        for (int mt = 0; mt < 4; mt++) { \
            uint32_t a0, a1, a2, a3; \
            uint32_t ad = ab + (wm * 64 + mt * 16 + lrow) * 128 + \
                          ((ks * 32 + lcol) ^ ((lrow & 7) << 4)); \
            LDMX4(a0, a1, a2, a3, ad); \
            _Pragma("unroll") \
            for (int nt = 0; nt < 4; nt++) MMAH(acc[mt][nt], a0, a1, a2, a3, b[nt]); \
        } \
    } \
} while (0)

// ---------------- GEMM B: Bus(re|im) = u (*) B_bar  (half output) ----------
// grid (nb4, slab4, f128), 512 thr. BM=256 px, BN=128, BK=64, 18 chunks.
__global__ __launch_bounds__(512, 1) void k_gemmB(int dummy) {
    extern __shared__ __align__(16) char smem[];
    int tid = threadIdx.x, lane = tid & 31, wid = tid >> 5;
    int wm = wid >> 2, wn = wid & 3;
    int g8 = lane >> 2, tig = lane & 3;
    int lrow = lane & 15, lcol = lane & 16;
    int nb = blockIdx.x, slab = blockIdx.y, f = blockIdx.z;
    int y0 = slab * 8;
    uint32_t abase = (uint32_t)__cvta_generic_to_shared(smem);
    uint32_t wbase = abase + 98304;

    float acc[4][4][4];
#pragma unroll
    for (int i = 0; i < 4; i++)
#pragma unroll
        for (int j = 0; j < 4; j++)
#pragma unroll
            for (int e = 0; e < 4; e++) acc[i][j][e] = 0.f;

#define ISSUE_B(s, k) do { \
    int tap = (k) >> 1, cb = (k) & 1; \
    int ky = tap / 3 - 1, kx = tap % 3 - 1; \
    _Pragma("unroll") \
    for (int q = 0; q < 4; q++) { \
        int idx = q * 512 + tid, m = idx >> 3, c8 = idx & 7; \
        int yy = y0 + (m >> 5) + ky, xx = (m & 31) + kx; \
        bool ok = ((unsigned)yy < 32u) && ((unsigned)xx < 32u); \
        const __half* src = g_u_h + ((((size_t)f * 32 + yy) * 32 + xx) << 7) + cb * 64 + c8 * 8; \
        uint32_t dst = abase + (s) * 32768 + m * 128 + ((c8 * 16) ^ ((m & 7) << 4)); \
        CP16(dst, src, ok); \
    } \
    const __half* wsrc = g_WBh + (((size_t)(k) * 4 + nb) << 13); \
    _Pragma("unroll") \
    for (int q = 0; q < 2; q++) { \
        int idx = q * 512 + tid; \
        CP16(wbase + (s) * 16384 + idx * 16, wsrc + idx * 8, true); \
    } \
} while (0)

    ISSUE_B(0, 0); CP_COMMIT();
    ISSUE_B(1, 1); CP_COMMIT();
    for (int k = 0; k < 18; k++) {
        int s = k % 3;
        if (k + 2 < 18) CP_WAIT1(); else CP_WAIT0();
        __syncthreads();
        if (k + 2 < 18) { ISSUE_B((k + 2) % 3, k + 2); CP_COMMIT(); }
        COMP(s);
    }

    __half* base = (nb < 2) ? (__half*)g_Bus_hre : (__half*)g_Bus_him;
    int ch0 = (nb & 1) * 128 + wn * 32;
#pragma unroll
    for (int mt = 0; mt < 4; mt++) {
        int m1 = wm * 64 + mt * 16 + g8, m2 = m1 + 8;
        size_t pix1 = (((size_t)f * 32 + y0 + (m1 >> 5)) * 32 + (m1 & 31)) * 256;
        size_t pix2 = (((size_t)f * 32 + y0 + (m2 >> 5)) * 32 + (m2 & 31)) * 256;
#pragma unroll
        for (int nt = 0; nt < 4; nt++) {
            int ch = ch0 + nt * 8 + tig * 2;
            *(__half2*)(base + pix1 + ch) = __floats2half2_rn(acc[mt][nt][0], acc[mt][nt][1]);
            *(__half2*)(base + pix2 + ch) = __floats2half2_rn(acc[mt][nt][2], acc[mt][nt][3]);
        }
    }
    (void)dummy;
}

// ---------------- K2: scan (half2 Bus in, half xs out, f32 x_last) ---------
__global__ __launch_bounds__(256) void k_scan(const float* __restrict__ x0,
                                              float* __restrict__ out) {
    int t = blockIdx.x * 256 + threadIdx.x;          // half2 index < SP/2
    int p0 = (2 * t) & 255;
    float ar0 = g_Are[p0],     ai0 = g_Aim[p0];
    float ar1 = g_Are[p0 + 1], ai1 = g_Aim[p0 + 1];
    float2 xv = ((const float2*)x0)[t];
    float xr0 = xv.x, xi0 = 0.f, xr1 = xv.y, xi1 = 0.f;
    size_t idx = (size_t)t;
#pragma unroll
    for (int l = 0; l < L_T; l++, idx += SP / 2) {
        float2 br = __half22float2(g_Bus_hre[idx]);
        float2 bi = __half22float2(g_Bus_him[idx]);
        float nr0 = fmaf(ar0, xr0, fmaf(-ai0, xi0, br.x));
        float ni0 = fmaf(ar0, xi0, fmaf( ai0, xr0, bi.x));
        float nr1 = fmaf(ar1, xr1, fmaf(-ai1, xi1, br.y));
        float ni1 = fmaf(ar1, xi1, fmaf( ai1, xr1, bi.y));
        xr0 = nr0; xi0 = ni0; xr1 = nr1; xi1 = ni1;
        ((__half2*)g_xh_re)[idx] = __floats2half2_rn(xr0, xr1);
        ((__half2*)g_xh_im)[idx] = __floats2half2_rn(xi0, xi1);
    }
    ((float4*)out)[t] = make_float4(xr0, xi0, xr1, xi1);
}

// ---------------- GEMM C: ys = 2Re(C (*) x) --------------------------------
// grid (slab4, f128), 512 thr. BM=256, BN=128, BK=64, 72 chunks.
__global__ __launch_bounds__(512, 1) void k_gemmC(int dummy) {
    extern __shared__ __align__(16) char smem[];
    int tid = threadIdx.x, lane = tid & 31, wid = tid >> 5;
    int wm = wid >> 2, wn = wid & 3;
    int g8 = lane >> 2, tig = lane & 3;
    int lrow = lane & 15, lcol = lane & 16;
    int slab = blockIdx.x, f = blockIdx.y;
    int y0 = slab * 8;
    uint32_t abase = (uint32_t)__cvta_generic_to_shared(smem);
    uint32_t wbase = abase + 98304;

    float acc[4][4][4];
#pragma unroll
    for (int i = 0; i < 4; i++)
#pragma unroll
        for (int j = 0; j < 4; j++)
#pragma unroll
            for (int e = 0; e < 4; e++) acc[i][j][e] = 0.f;

#define ISSUE_C(s, k) do { \
    int tap = (k) >> 3, kc8 = (k) & 7; \
    const __half* srcb = (kc8 < 4) ? g_xh_re : g_xh_im; \
    int c0 = (kc8 & 3) * 64; \
    int ky = tap / 3 - 1, kx = tap % 3 - 1; \
    _Pragma("unroll") \
    for (int q = 0; q < 4; q++) { \
        int idx = q * 512 + tid, m = idx >> 3, c8 = idx & 7; \
        int yy = y0 + (m >> 5) + ky, xx = (m & 31) + kx; \
        bool ok = ((unsigned)yy < 32u) && ((unsigned)xx < 32u); \
        const __half* src = srcb + ((((size_t)f * 32 + yy) * 32 + xx) << 8) + c0 + c8 * 8; \
        uint32_t dst = abase + (s) * 32768 + m * 128 + ((c8 * 16) ^ ((m & 7) << 4)); \
        CP16(dst, src, ok); \
    } \
    const __half* wsrc = g_WCh + ((size_t)(k) << 13); \
    _Pragma("unroll") \
    for (int q = 0; q < 2; q++) { \
        int idx = q * 512 + tid; \
        CP16(wbase + (s) * 16384 + idx * 16, wsrc + idx * 8, true); \
    } \
} while (0)

    ISSUE_C(0, 0); CP_COMMIT();
    ISSUE_C(1, 1); CP_COMMIT();
    for (int k = 0; k < 72; k++) {
        int s = k % 3;
        if (k + 2 < 72) CP_WAIT1(); else CP_WAIT0();
        __syncthreads();
        if (k + 2 < 72) { ISSUE_C((k + 2) % 3, k + 2); CP_COMMIT(); }
        COMP(s);
    }

#pragma unroll
    for (int mt = 0; mt < 4; mt++) {
        int m1 = wm * 64 + mt * 16 + g8, m2 = m1 + 8;
        size_t pix1 = (((size_t)f * 32 + y0 + (m1 >> 5)) * 32 + (m1 & 31)) * 128;
        size_t pix2 = (((size_t)f * 32 + y0 + (m2 >> 5)) * 32 + (m2 & 31)) * 128;
#pragma unroll
        for (int nt = 0; nt < 4; nt++) {
            int ch = wn * 32 + nt * 8 + tig * 2;
            *(float2*)(g_ys + pix1 + ch) = make_float2(acc[mt][nt][0], acc[mt][nt][1]);
            *(float2*)(g_ys + pix2 + ch) = make_float2(acc[mt][nt][2], acc[mt][nt][3]);
        }
    }
    (void)dummy;
}

// ---------------- K3b: depthwise D feedthrough (f32, coalesced) ------------
__global__ __launch_bounds__(128) void k_dw(const float* __restrict__ u_in,
                                            const float* __restrict__ Dk) {
    int f = blockIdx.x, y = blockIdx.y, u = threadIdx.x;
    float dk[9];
#pragma unroll
    for (int j = 0; j < 9; j++) dk[j] = Dk[j * U_ + u];
    float acc[W_];
#pragma unroll
    for (int x = 0; x < W_; x++) acc[x] = 0.f;
    for (int ky = 0; ky < 3; ky++) {
        int yi = y + ky - 1;
        if (yi < 0 || yi >= H_) continue;
        const float* row = u_in + ((size_t)(f * H_ + yi) * W_) * U_ + u;
        float v0 = 0.f, v1 = row[0];
#pragma unroll
        for (int x = 0; x < W_; x++) {
            float v2 = (x + 1 < W_) ? row[(x + 1) * U_] : 0.f;
            acc[x] = fmaf(v0, dk[ky * 3], fmaf(v1, dk[ky * 3 + 1], fmaf(v2, dk[ky * 3 + 2], acc[x])));
            v0 = v1; v1 = v2;
        }
    }
    size_t base = ((size_t)(f * H_ + y) * W_) * U_ + u;
#pragma unroll
    for (int x = 0; x < W_; x++) g_ys[base + (size_t)x * U_] += acc[x];
}

// ---------------- K4: GroupNorm(32) + tanh-GELU ----------------------------
__global__ __launch_bounds__(256) void k_gn(const float* __restrict__ scale,
                                            const float* __restrict__ bias,
                                            float* __restrict__ out) {
    int f = blockIdx.x, g = blockIdx.y;
    size_t base = (size_t)f * (H_ * W_ * U_) + g * 4;

    float s = 0.f, s2 = 0.f;
    for (int j = threadIdx.x; j < H_ * W_ * 4; j += 256) {
        int yx = j >> 2, cl = j & 3;
        float v = g_ys[base + (size_t)yx * U_ + cl];
        s += v; s2 += v * v;
    }
    __shared__ float rs[8], rs2[8];
    unsigned m = 0xffffffffu;
#pragma unroll
    for (int o = 16; o > 0; o >>= 1) {
        s  += __shfl_down_sync(m, s, o);
        s2 += __shfl_down_sync(m, s2, o);
    }
    if ((threadIdx.x & 31) == 0) { rs[threadIdx.x >> 5] = s; rs2[threadIdx.x >> 5] = s2; }
    __syncthreads();
    if (threadIdx.x == 0) {
        float ts = 0.f, ts2 = 0.f;
#pragma unroll
        for (int i = 0; i < 8; i++) { ts += rs[i]; ts2 += rs2[i]; }
        float mu  = ts * (1.f / 4096.f);
        float var = ts2 * (1.f / 4096.f) - mu * mu;
        rs[0]  = mu;
        rs2[0] = rsqrtf(var + EPS_GN);
    }
    __syncthreads();
    float mu = rs[0], rstd = rs2[0];

    float sc[4], bi[4];
#pragma unroll
    for (int c = 0; c < 4; c++) { sc[c] = scale[g * 4 + c]; bi[c] = bias[g * 4 + c]; }

    float* outy = out + (size_t)SP * 2;
    for (int j = threadIdx.x; j < H_ * W_ * 4; j += 256) {
        int yx = j >> 2, cl = j & 3;
        size_t idx = base + (size_t)yx * U_ + cl;
        float v = g_ys[idx];
        float h = (v - mu) * rstd * sc[cl] + bi[cl];
        float t = 0.7978845608028654f * (h + 0.044715f * h * h * h);
        outy[idx] = 0.5f * h * (1.f + tanhf(t));
    }
}

// ---------------- launch ----------------
extern "C" void kernel_launch(void* const* d_in, const int* in_sizes, int n_in,
                              void* d_out, int out_size) {
    const float* u_in  = (const float*)d_in[0];
    const float* x0    = (const float*)d_in[1];
    const float* Lre   = (const float*)d_in[2];
    const float* Lim   = (const float*)d_in[3];
    const float* B_ri  = (const float*)d_in[4];
    const float* C_ri  = (const float*)d_in[5];
    const float* lstep = (const float*)d_in[6];
    const float* Dk    = (const float*)d_in[7];
    const float* gsc   = (const float*)d_in[8];
    const float* gbi   = (const float*)d_in[9];
    float* out = (float*)d_out;
    (void)in_sizes; (void)n_in; (void)out_size;

    cudaFuncSetAttribute(k_gemmB, cudaFuncAttributeMaxDynamicSharedMemorySize, SMEM_GEMM);
    cudaFuncSetAttribute(k_gemmC, cudaFuncAttributeMaxDynamicSharedMemorySize, SMEM_GEMM);

    k_pre<<<(NB_W + NC_W + 255) / 256, 256>>>(Lre, Lim, lstep, B_ri, C_ri);
    k_uh<<<U_N / 4 / 256, 256>>>(u_in);
    k_gemmB<<<dim3(4, 4, FRAMES), 512, SMEM_GEMM>>>(0);
    k_scan<<<SP / 2 / 256, 256>>>(x0, out);
    k_gemmC<<<dim3(4, FRAMES), 512, SMEM_GEMM>>>(0);
    k_dw<<<dim3(FRAMES, H_), 128>>>(u_in, Dk);
    k_gn<<<dim3(FRAMES, 32), 256>>>(gsc, gbi, out);
}

// round 9
// speedup vs baseline: 1.1691x; 1.1044x over previous
#include <cuda_runtime.h>
#include <cuda_fp16.h>
#include <cstdint>

// ---------------- problem constants ----------------
#define L_T   16
#define BSZ   8
#define H_    32
#define W_    32
#define U_    128
#define P_    256
#define FRAMES 128
#define SP    (BSZ*H_*W_*P_)      // 2,097,152
#define YS_N  (L_T*BSZ*H_*W_*U_)  // 16,777,216
#define BUS_N (L_T*BSZ*H_*W_*P_)  // 33,554,432
#define U_N   (L_T*BSZ*H_*W_*U_)  // 16,777,216
#define EPS_GN 1e-5f

#define NB_W  589824   // half: [chunk9][nb4][wn4][nt4][ks8][lane32][reg2][h2]
#define NC_W  589824   // half: [half2][chunk18][wn4][nt4][ks8][lane32][reg2][h2]

#define SMEM_GEMM 196608   // 2 stages x (64KB A + 32KB W)

// ---------------- device scratch (allocation-free) ----------------
__device__ __align__(16) __half g_WBh[NB_W];
__device__ __align__(16) __half g_WCh[NC_W];
__device__ float g_Are[P_];
__device__ float g_Aim[P_];
__device__ __align__(16) __half g_u_h[U_N];
__device__ __align__(16) __half2 g_Bus_hre[BUS_N / 2];
__device__ __align__(16) __half2 g_Bus_him[BUS_N / 2];
__device__ __align__(16) __half g_xh_re[BUS_N];
__device__ __align__(16) __half g_xh_im[BUS_N];
__device__ __align__(16) float g_ys[YS_N];
__device__ __align__(16) float g_ys2[YS_N];

#define LDMX4(r0, r1, r2, r3, addr) \
    asm volatile("ldmatrix.sync.aligned.m8n8.x4.shared.b16 {%0,%1,%2,%3}, [%4];" \
                 : "=r"(r0), "=r"(r1), "=r"(r2), "=r"(r3) : "r"(addr))

#define MMAH(c, a0, a1, a2, a3, b) asm volatile( \
    "mma.sync.aligned.m16n8k16.row.col.f32.f16.f16.f32 " \
    "{%0,%1,%2,%3},{%4,%5,%6,%7},{%8,%9},{%0,%1,%2,%3};" \
    : "+f"((c)[0]), "+f"((c)[1]), "+f"((c)[2]), "+f"((c)[3]) \
    : "r"(a0), "r"(a1), "r"(a2), "r"(a3), "r"((b).x), "r"((b).y))

#define CP16(dst, src, pred) do { \
    int _sz = (pred) ? 16 : 0; \
    asm volatile("cp.async.cg.shared.global [%0], [%1], 16, %2;" \
                 :: "r"(dst), "l"(src), "r"(_sz)); \
} while (0)

#define CP_COMMIT() asm volatile("cp.async.commit_group;" ::: "memory")
#define CP_WAIT0()  asm volatile("cp.async.wait_group 0;" ::: "memory")

// ---------------- K0: discretization + weight fragment pre-permute (half) --
__global__ void k_pre(const float* __restrict__ Lre, const float* __restrict__ Lim,
                      const float* __restrict__ lstep,
                      const float* __restrict__ B_ri, const float* __restrict__ C_ri) {
    int tid = blockIdx.x * blockDim.x + threadIdx.x;
    if (tid < P_) {
        float st = expf(lstep[tid]);
        g_Are[tid] = fminf(Lre[tid], -1e-4f) * st;
        g_Aim[tid] = Lim[tid] * st;
    }
    if (tid < NB_W) {
        int h = tid & 1, reg = (tid >> 1) & 1, lane = (tid >> 2) & 31;
        int ks = (tid >> 7) & 7, nt = (tid >> 10) & 3, wn = (tid >> 12) & 3;
        int nb = (tid >> 14) & 3, chunk = tid >> 16;            // 0..8 (= tap)
        int c = ks * 16 + reg * 8 + (lane & 3) * 2 + h;         // 0..127
        int n = nb * 128 + wn * 32 + nt * 8 + (lane >> 2);
        int plane = n >> 8, p = n & 255;
        float v = B_ri[(((size_t)p * 128 + c) * 9 + chunk) * 2 + plane] * expf(lstep[p]);
        g_WBh[tid] = __float2half_rn(v);
    }
    int t2 = tid - NB_W;
    if (t2 >= 0 && t2 < NC_W) {
        int h = t2 & 1, reg = (t2 >> 1) & 1, lane = (t2 >> 2) & 31;
        int ks = (t2 >> 7) & 7, nt = (t2 >> 10) & 3, wn = (t2 >> 12) & 3;
        int rest = t2 >> 14;                                    // 0..35
        int half = rest / 18, kc = rest % 18;
        int tap = kc >> 1;
        int p = (kc & 1) * 128 + ks * 16 + reg * 8 + (lane & 3) * 2 + h;
        int u = wn * 32 + nt * 8 + (lane >> 2);
        float v = (half == 0)
            ?  2.f * C_ri[(((size_t)u * 256 + p) * 9 + tap) * 2]
            : -2.f * C_ri[(((size_t)u * 256 + p) * 9 + tap) * 2 + 1];
        g_WCh[t2] = __float2half_rn(v);
    }
}

// ---------------- K0b: input f32 -> half -----------------------------------
__global__ void k_uh(const float* __restrict__ u_in) {
    int i = blockIdx.x * blockDim.x + threadIdx.x;
    float4 v = ((const float4*)u_in)[i];
    __half2* dst = (__half2*)g_u_h;
    dst[2 * i]     = __floats2half2_rn(v.x, v.y);
    dst[2 * i + 1] = __floats2half2_rn(v.z, v.w);
}

// ---------------- shared GEMM compute macro (fp16, BK=128) -----------------
// A stage: 256 rows x 256B (swizzled); W stage: [wn][nt][ks8][lane] uint2.
#define COMP(s) do { \
    uint32_t ab = abase + (s) * 65536; \
    uint32_t wb = wbase + (s) * 32768; \
    _Pragma("unroll") \
    for (int ks = 0; ks < 8; ks++) { \
        uint2 b[4]; \
        _Pragma("unroll") \
        for (int nt = 0; nt < 4; nt++) { \
            uint32_t waddr = wb + ((((wn * 4 + nt) * 8 + ks) * 32 + lane) << 3); \
            asm volatile("ld.shared.v2.b32 {%0,%1}, [%2];" \
                         : "=r"(b[nt].x), "=r"(b[nt].y) : "r"(waddr)); \
        } \
        _Pragma("unroll") \
        for (int mt = 0; mt < 4; mt++) { \
            uint32_t a0, a1, a2, a3; \
            uint32_t ad = ab + (wm * 64 + mt * 16 + lrow) * 256 + \
                          ((ks * 32 + lcol) ^ ((lrow & 7) << 4)); \
            LDMX4(a0, a1, a2, a3, ad); \
            _Pragma("unroll") \
            for (int nt = 0; nt < 4; nt++) MMAH(acc[mt][nt], a0, a1, a2, a3, b[nt]); \
        } \
    } \
} while (0)

// ---------------- GEMM B: Bus(re|im) = u (*) B_bar  (half output) ----------
// grid (nb4, slab4, f128), 512 thr. BM=256 px, BN=128, BK=128, 9 chunks (=taps).
__global__ __launch_bounds__(512, 1) void k_gemmB(int dummy) {
    extern __shared__ __align__(16) char smem[];
    int tid = threadIdx.x, lane = tid & 31, wid = tid >> 5;
    int wm = wid >> 2, wn = wid & 3;
    int g8 = lane >> 2, tig = lane & 3;
    int lrow = lane & 15, lcol = lane & 16;
    int nb = blockIdx.x, slab = blockIdx.y, f = blockIdx.z;
    int y0 = slab * 8;
    uint32_t abase = (uint32_t)__cvta_generic_to_shared(smem);
    uint32_t wbase = abase + 131072;

    float acc[4][4][4];
#pragma unroll
    for (int i = 0; i < 4; i++)
#pragma unroll
        for (int j = 0; j < 4; j++)
#pragma unroll
            for (int e = 0; e < 4; e++) acc[i][j][e] = 0.f;

#define ISSUE_B(s, k) do { \
    int ky = (k) / 3 - 1, kx = (k) % 3 - 1; \
    _Pragma("unroll") \
    for (int q = 0; q < 8; q++) { \
        int idx = q * 512 + tid, m = idx >> 4, c16 = idx & 15; \
        int yy = y0 + (m >> 5) + ky, xx = (m & 31) + kx; \
        bool ok = ((unsigned)yy < 32u) && ((unsigned)xx < 32u); \
        const __half* src = g_u_h + ((((size_t)f * 32 + yy) * 32 + xx) << 7) + c16 * 8; \
        uint32_t dst = abase + (s) * 65536 + m * 256 + ((c16 * 16) ^ ((m & 7) << 4)); \
        CP16(dst, src, ok); \
    } \
    const __half* wsrc = g_WBh + (((size_t)(k) * 4 + nb) << 14); \
    _Pragma("unroll") \
    for (int q = 0; q < 4; q++) { \
        int idx = q * 512 + tid; \
        CP16(wbase + (s) * 32768 + idx * 16, wsrc + idx * 8, true); \
    } \
} while (0)

    ISSUE_B(0, 0); CP_COMMIT();
    for (int k = 0; k < 9; k++) {
        CP_WAIT0();
        __syncthreads();
        if (k + 1 < 9) { ISSUE_B((k + 1) & 1, k + 1); CP_COMMIT(); }
        COMP(k & 1);
    }

    __half* base = (nb < 2) ? (__half*)g_Bus_hre : (__half*)g_Bus_him;
    int ch0 = (nb & 1) * 128 + wn * 32;
#pragma unroll
    for (int mt = 0; mt < 4; mt++) {
        int m1 = wm * 64 + mt * 16 + g8, m2 = m1 + 8;
        size_t pix1 = (((size_t)f * 32 + y0 + (m1 >> 5)) * 32 + (m1 & 31)) * 256;
        size_t pix2 = (((size_t)f * 32 + y0 + (m2 >> 5)) * 32 + (m2 & 31)) * 256;
#pragma unroll
        for (int nt = 0; nt < 4; nt++) {
            int ch = ch0 + nt * 8 + tig * 2;
            *(__half2*)(base + pix1 + ch) = __floats2half2_rn(acc[mt][nt][0], acc[mt][nt][1]);
            *(__half2*)(base + pix2 + ch) = __floats2half2_rn(acc[mt][nt][2], acc[mt][nt][3]);
        }
    }
    (void)dummy;
}

// ---------------- K2: scan (half2 Bus in, half xs out, f32 x_last) ---------
__global__ __launch_bounds__(256) void k_scan(const float* __restrict__ x0,
                                              float* __restrict__ out) {
    int t = blockIdx.x * 256 + threadIdx.x;
    int p0 = (2 * t) & 255;
    float ar0 = g_Are[p0],     ai0 = g_Aim[p0];
    float ar1 = g_Are[p0 + 1], ai1 = g_Aim[p0 + 1];
    float2 xv = ((const float2*)x0)[t];
    float xr0 = xv.x, xi0 = 0.f, xr1 = xv.y, xi1 = 0.f;
    size_t idx = (size_t)t;
#pragma unroll
    for (int l = 0; l < L_T; l++, idx += SP / 2) {
        float2 br = __half22float2(g_Bus_hre[idx]);
        float2 bi = __half22float2(g_Bus_him[idx]);
        float nr0 = fmaf(ar0, xr0, fmaf(-ai0, xi0, br.x));
        float ni0 = fmaf(ar0, xi0, fmaf( ai0, xr0, bi.x));
        float nr1 = fmaf(ar1, xr1, fmaf(-ai1, xi1, br.y));
        float ni1 = fmaf(ar1, xi1, fmaf( ai1, xr1, bi.y));
        xr0 = nr0; xi0 = ni0; xr1 = nr1; xi1 = ni1;
        ((__half2*)g_xh_re)[idx] = __floats2half2_rn(xr0, xr1);
        ((__half2*)g_xh_im)[idx] = __floats2half2_rn(xi0, xi1);
    }
    ((float4*)out)[t] = make_float4(xr0, xi0, xr1, xi1);
}

// ---------------- GEMM C: ys = 2Re(C (*) x), K-split re/im -----------------
// grid (slab4, f128, half2), 512 thr. BM=256, BN=128, BK=128, 18 chunks.
__global__ __launch_bounds__(512, 1) void k_gemmC(int dummy) {
    extern __shared__ __align__(16) char smem[];
    int tid = threadIdx.x, lane = tid & 31, wid = tid >> 5;
    int wm = wid >> 2, wn = wid & 3;
    int g8 = lane >> 2, tig = lane & 3;
    int lrow = lane & 15, lcol = lane & 16;
    int slab = blockIdx.x, f = blockIdx.y, half = blockIdx.z;
    int y0 = slab * 8;
    const __half* srcb = half ? g_xh_im : g_xh_re;
    uint32_t abase = (uint32_t)__cvta_generic_to_shared(smem);
    uint32_t wbase = abase + 131072;

    float acc[4][4][4];
#pragma unroll
    for (int i = 0; i < 4; i++)
#pragma unroll
        for (int j = 0; j < 4; j++)
#pragma unroll
            for (int e = 0; e < 4; e++) acc[i][j][e] = 0.f;

#define ISSUE_C(s, k) do { \
    int tap = (k) >> 1, cb = (k) & 1; \
    int ky = tap / 3 - 1, kx = tap % 3 - 1; \
    _Pragma("unroll") \
    for (int q = 0; q < 8; q++) { \
        int idx = q * 512 + tid, m = idx >> 4, c16 = idx & 15; \
        int yy = y0 + (m >> 5) + ky, xx = (m & 31) + kx; \
        bool ok = ((unsigned)yy < 32u) && ((unsigned)xx < 32u); \
        const __half* src = srcb + ((((size_t)f * 32 + yy) * 32 + xx) << 8) + cb * 128 + c16 * 8; \
        uint32_t dst = abase + (s) * 65536 + m * 256 + ((c16 * 16) ^ ((m & 7) << 4)); \
        CP16(dst, src, ok); \
    } \
    const __half* wsrc = g_WCh + (((size_t)half * 18 + (k)) << 14); \
    _Pragma("unroll") \
    for (int q = 0; q < 4; q++) { \
        int idx = q * 512 + tid; \
        CP16(wbase + (s) * 32768 + idx * 16, wsrc + idx * 8, true); \
    } \
} while (0)

    ISSUE_C(0, 0); CP_COMMIT();
    for (int k = 0; k < 18; k++) {
        CP_WAIT0();
        __syncthreads();
        if (k + 1 < 18) { ISSUE_C((k + 1) & 1, k + 1); CP_COMMIT(); }
        COMP(k & 1);
    }

    float* ybase = half ? g_ys2 : g_ys;
#pragma unroll
    for (int mt = 0; mt < 4; mt++) {
        int m1 = wm * 64 + mt * 16 + g8, m2 = m1 + 8;
        size_t pix1 = (((size_t)f * 32 + y0 + (m1 >> 5)) * 32 + (m1 & 31)) * 128;
        size_t pix2 = (((size_t)f * 32 + y0 + (m2 >> 5)) * 32 + (m2 & 31)) * 128;
#pragma unroll
        for (int nt = 0; nt < 4; nt++) {
            int ch = wn * 32 + nt * 8 + tig * 2;
            *(float2*)(ybase + pix1 + ch) = make_float2(acc[mt][nt][0], acc[mt][nt][1]);
            *(float2*)(ybase + pix2 + ch) = make_float2(acc[mt][nt][2], acc[mt][nt][3]);
        }
    }
    (void)dummy;
}

// ---------------- K3b: depthwise D feedthrough (f32, coalesced) ------------
__global__ __launch_bounds__(128) void k_dw(const float* __restrict__ u_in,
                                            const float* __restrict__ Dk) {
    int f = blockIdx.x, y = blockIdx.y, u = threadIdx.x;
    float dk[9];
#pragma unroll
    for (int j = 0; j < 9; j++) dk[j] = Dk[j * U_ + u];
    float acc[W_];
#pragma unroll
    for (int x = 0; x < W_; x++) acc[x] = 0.f;
    for (int ky = 0; ky < 3; ky++) {
        int yi = y + ky - 1;
        if (yi < 0 || yi >= H_) continue;
        const float* row = u_in + ((size_t)(f * H_ + yi) * W_) * U_ + u;
        float v0 = 0.f, v1 = row[0];
#pragma unroll
        for (int x = 0; x < W_; x++) {
            float v2 = (x + 1 < W_) ? row[(x + 1) * U_] : 0.f;
            acc[x] = fmaf(v0, dk[ky * 3], fmaf(v1, dk[ky * 3 + 1], fmaf(v2, dk[ky * 3 + 2], acc[x])));
            v0 = v1; v1 = v2;
        }
    }
    size_t base = ((size_t)(f * H_ + y) * W_) * U_ + u;
#pragma unroll
    for (int x = 0; x < W_; x++) g_ys[base + (size_t)x * U_] += acc[x];
}

// ---------------- K4: GroupNorm(32) + tanh-GELU (sums ys + ys2) ------------
__global__ __launch_bounds__(256) void k_gn(const float* __restrict__ scale,
                                            const float* __restrict__ bias,
                                            float* __restrict__ out) {
    int f = blockIdx.x, g = blockIdx.y;
    size_t base = (size_t)f * (H_ * W_ * U_) + g * 4;

    float s = 0.f, s2 = 0.f;
    for (int j = threadIdx.x; j < H_ * W_ * 4; j += 256) {
        int yx = j >> 2, cl = j & 3;
        size_t idx = base + (size_t)yx * U_ + cl;
        float v = g_ys[idx] + g_ys2[idx];
        s += v; s2 += v * v;
    }
    __shared__ float rs[8], rs2[8];
    unsigned m = 0xffffffffu;
#pragma unroll
    for (int o = 16; o > 0; o >>= 1) {
        s  += __shfl_down_sync(m, s, o);
        s2 += __shfl_down_sync(m, s2, o);
    }
    if ((threadIdx.x & 31) == 0) { rs[threadIdx.x >> 5] = s; rs2[threadIdx.x >> 5] = s2; }
    __syncthreads();
    if (threadIdx.x == 0) {
        float ts = 0.f, ts2 = 0.f;
#pragma unroll
        for (int i = 0; i < 8; i++) { ts += rs[i]; ts2 += rs2[i]; }
        float mu  = ts * (1.f / 4096.f);
        float var = ts2 * (1.f / 4096.f) - mu * mu;
        rs[0]  = mu;
        rs2[0] = rsqrtf(var + EPS_GN);
    }
    __syncthreads();
    float mu = rs[0], rstd = rs2[0];

    float sc[4], bi[4];
#pragma unroll
    for (int c = 0; c < 4; c++) { sc[c] = scale[g * 4 + c]; bi[c] = bias[g * 4 + c]; }

    float* outy = out + (size_t)SP * 2;
    for (int j = threadIdx.x; j < H_ * W_ * 4; j += 256) {
        int yx = j >> 2, cl = j & 3;
        size_t idx = base + (size_t)yx * U_ + cl;
        float v = g_ys[idx] + g_ys2[idx];
        float h = (v - mu) * rstd * sc[cl] + bi[cl];
        float t = 0.7978845608028654f * (h + 0.044715f * h * h * h);
        outy[idx] = 0.5f * h * (1.f + tanhf(t));
    }
}

// ---------------- launch ----------------
extern "C" void kernel_launch(void* const* d_in, const int* in_sizes, int n_in,
                              void* d_out, int out_size) {
    const float* u_in  = (const float*)d_in[0];
    const float* x0    = (const float*)d_in[1];
    const float* Lre   = (const float*)d_in[2];
    const float* Lim   = (const float*)d_in[3];
    const float* B_ri  = (const float*)d_in[4];
    const float* C_ri  = (const float*)d_in[5];
    const float* lstep = (const float*)d_in[6];
    const float* Dk    = (const float*)d_in[7];
    const float* gsc   = (const float*)d_in[8];
    const float* gbi   = (const float*)d_in[9];
    float* out = (float*)d_out;
    (void)in_sizes; (void)n_in; (void)out_size;

    cudaFuncSetAttribute(k_gemmB, cudaFuncAttributeMaxDynamicSharedMemorySize, SMEM_GEMM);
    cudaFuncSetAttribute(k_gemmC, cudaFuncAttributeMaxDynamicSharedMemorySize, SMEM_GEMM);

    k_pre<<<(NB_W + NC_W + 255) / 256, 256>>>(Lre, Lim, lstep, B_ri, C_ri);
    k_uh<<<U_N / 4 / 256, 256>>>(u_in);
    k_gemmB<<<dim3(4, 4, FRAMES), 512, SMEM_GEMM>>>(0);
    k_scan<<<SP / 2 / 256, 256>>>(x0, out);
    k_gemmC<<<dim3(4, FRAMES, 2), 512, SMEM_GEMM>>>(0);
    k_dw<<<dim3(FRAMES, H_), 128>>>(u_in, Dk);
    k_gn<<<dim3(FRAMES, 32), 256>>>(gsc, gbi, out);
}

// round 10
// speedup vs baseline: 1.1814x; 1.0106x over previous
#include <cuda_runtime.h>
#include <cuda_fp16.h>
#include <cstdint>

// ---------------- problem constants ----------------
#define L_T   16
#define BSZ   8
#define H_    32
#define W_    32
#define U_    128
#define P_    256
#define FRAMES 128
#define SP    (BSZ*H_*W_*P_)      // 2,097,152
#define YS_N  (L_T*BSZ*H_*W_*U_)  // 16,777,216
#define BUS_N (L_T*BSZ*H_*W_*P_)  // 33,554,432
#define U_N   (L_T*BSZ*H_*W_*U_)  // 16,777,216
#define EPS_GN 1e-5f

#define NB_W  589824   // half: [tap9][nb4][wn4][nt4][ks8][lane32][reg2][h2]
#define NC_W  589824   // half: [half2][cb2*tap9][wn4][nt4][ks8][lane32][reg2][h2]

#define HALO_BYTES 87040         // 340 rows x 256B (10x34 px halo, swizzled)
#define SMEM_GEMM  (HALO_BYTES + 3*32768)   // 185,344

// ---------------- device scratch (allocation-free) ----------------
__device__ __align__(16) __half g_WBh[NB_W];
__device__ __align__(16) __half g_WCh[NC_W];
__device__ float g_Are[P_];
__device__ float g_Aim[P_];
__device__ __align__(16) __half g_u_h[U_N];
__device__ __align__(16) __half2 g_Bus_hre[BUS_N / 2];
__device__ __align__(16) __half2 g_Bus_him[BUS_N / 2];
__device__ __align__(16) __half g_xh_re[BUS_N];
__device__ __align__(16) __half g_xh_im[BUS_N];
__device__ __align__(16) float g_ys[YS_N];
__device__ __align__(16) float g_ys2[YS_N];

#define LDMX4(r0, r1, r2, r3, addr) \
    asm volatile("ldmatrix.sync.aligned.m8n8.x4.shared.b16 {%0,%1,%2,%3}, [%4];" \
                 : "=r"(r0), "=r"(r1), "=r"(r2), "=r"(r3) : "r"(addr))

#define MMAH(c, a0, a1, a2, a3, b) asm volatile( \
    "mma.sync.aligned.m16n8k16.row.col.f32.f16.f16.f32 " \
    "{%0,%1,%2,%3},{%4,%5,%6,%7},{%8,%9},{%0,%1,%2,%3};" \
    : "+f"((c)[0]), "+f"((c)[1]), "+f"((c)[2]), "+f"((c)[3]) \
    : "r"(a0), "r"(a1), "r"(a2), "r"(a3), "r"((b).x), "r"((b).y))

#define CP16(dst, src, pred) do { \
    int _sz = (pred) ? 16 : 0; \
    asm volatile("cp.async.cg.shared.global [%0], [%1], 16, %2;" \
                 :: "r"(dst), "l"(src), "r"(_sz)); \
} while (0)

#define CP_COMMIT() asm volatile("cp.async.commit_group;" ::: "memory")
#define CP_WAIT1()  asm volatile("cp.async.wait_group 1;" ::: "memory")
#define CP_WAIT0()  asm volatile("cp.async.wait_group 0;" ::: "memory")

// ---------------- K0: discretization + weight fragment pre-permute (half) --
__global__ void k_pre(const float* __restrict__ Lre, const float* __restrict__ Lim,
                      const float* __restrict__ lstep,
                      const float* __restrict__ B_ri, const float* __restrict__ C_ri) {
    int tid = blockIdx.x * blockDim.x + threadIdx.x;
    if (tid < P_) {
        float st = expf(lstep[tid]);
        g_Are[tid] = fminf(Lre[tid], -1e-4f) * st;
        g_Aim[tid] = Lim[tid] * st;
    }
    if (tid < NB_W) {
        int h = tid & 1, reg = (tid >> 1) & 1, lane = (tid >> 2) & 31;
        int ks = (tid >> 7) & 7, nt = (tid >> 10) & 3, wn = (tid >> 12) & 3;
        int nb = (tid >> 14) & 3, tap = tid >> 16;              // 0..8
        int c = ks * 16 + reg * 8 + (lane & 3) * 2 + h;         // 0..127
        int n = nb * 128 + wn * 32 + nt * 8 + (lane >> 2);
        int plane = n >> 8, p = n & 255;
        float v = B_ri[(((size_t)p * 128 + c) * 9 + tap) * 2 + plane] * expf(lstep[p]);
        g_WBh[tid] = __float2half_rn(v);
    }
    int t2 = tid - NB_W;
    if (t2 >= 0 && t2 < NC_W) {
        int h = t2 & 1, reg = (t2 >> 1) & 1, lane = (t2 >> 2) & 31;
        int ks = (t2 >> 7) & 7, nt = (t2 >> 10) & 3, wn = (t2 >> 12) & 3;
        int rest = t2 >> 14;                                    // 0..35
        int half = rest / 18, kc = rest % 18;
        int cb = kc / 9, tap = kc % 9;                          // cb-major, tap-minor
        int p = cb * 128 + ks * 16 + reg * 8 + (lane & 3) * 2 + h;
        int u = wn * 32 + nt * 8 + (lane >> 2);
        float v = (half == 0)
            ?  2.f * C_ri[(((size_t)u * 256 + p) * 9 + tap) * 2]
            : -2.f * C_ri[(((size_t)u * 256 + p) * 9 + tap) * 2 + 1];
        g_WCh[t2] = __float2half_rn(v);
    }
}

// ---------------- K0b: input f32 -> half -----------------------------------
__global__ void k_uh(const float* __restrict__ u_in) {
    int i = blockIdx.x * blockDim.x + threadIdx.x;
    float4 v = ((const float4*)u_in)[i];
    __half2* dst = (__half2*)g_u_h;
    dst[2 * i]     = __floats2half2_rn(v.x, v.y);
    dst[2 * i + 1] = __floats2half2_rn(v.z, v.w);
}

// -------- compute macro: A from halo tile (per-tap addressing), W stage s --
// halo rows r = (my+ky)*34 + mx + kx + lrow, 256B/row, XOR-16B swizzle.
#define COMPH(s, ky, kx) do { \
    uint32_t wb = wbase + (s) * 32768; \
    int rr[4]; \
    _Pragma("unroll") \
    for (int mt = 0; mt < 4; mt++) { \
        int m0 = wm * 64 + mt * 16; \
        rr[mt] = ((m0 >> 5) + (ky)) * 34 + (m0 & 31) + (kx) + lrow; \
    } \
    _Pragma("unroll") \
    for (int ks = 0; ks < 8; ks++) { \
        uint2 b[4]; \
        _Pragma("unroll") \
        for (int nt = 0; nt < 4; nt++) { \
            uint32_t waddr = wb + ((((wn * 4 + nt) * 8 + ks) * 32 + lane) << 3); \
            asm volatile("ld.shared.v2.b32 {%0,%1}, [%2];" \
                         : "=r"(b[nt].x), "=r"(b[nt].y) : "r"(waddr)); \
        } \
        _Pragma("unroll") \
        for (int mt = 0; mt < 4; mt++) { \
            uint32_t a0, a1, a2, a3; \
            uint32_t ad = abase + rr[mt] * 256 + \
                          ((ks * 32 + lcol) ^ ((rr[mt] & 7) << 4)); \
            LDMX4(a0, a1, a2, a3, ad); \
            _Pragma("unroll") \
            for (int nt = 0; nt < 4; nt++) MMAH(acc[mt][nt], a0, a1, a2, a3, b[nt]); \
        } \
    } \
} while (0)

// ---------------- GEMM B: Bus(re|im) = u (*) B_bar  (half output) ----------
// grid (nb4, slab4, f128), 512 thr. BM=256 px, BN=128, BK=128, 9 taps.
__global__ __launch_bounds__(512, 1) void k_gemmB(int dummy) {
    extern __shared__ __align__(16) char smem[];
    int tid = threadIdx.x, lane = tid & 31, wid = tid >> 5;
    int wm = wid >> 2, wn = wid & 3;
    int g8 = lane >> 2, tig = lane & 3;
    int lrow = lane & 15, lcol = lane & 16;
    int nb = blockIdx.x, slab = blockIdx.y, f = blockIdx.z;
    int y0 = slab * 8;
    uint32_t abase = (uint32_t)__cvta_generic_to_shared(smem);
    uint32_t wbase = abase + HALO_BYTES;

    float acc[4][4][4];
#pragma unroll
    for (int i = 0; i < 4; i++)
#pragma unroll
        for (int j = 0; j < 4; j++)
#pragma unroll
            for (int e = 0; e < 4; e++) acc[i][j][e] = 0.f;

    // halo load: 340 rows x 16 16B-chunks
    for (int idx = tid; idx < 5440; idx += 512) {
        int r = idx >> 4, c16 = idx & 15;
        int hy = r / 34, hx = r - hy * 34;
        int yy = y0 + hy - 1, xx = hx - 1;
        bool ok = ((unsigned)yy < 32u) && ((unsigned)xx < 32u);
        const __half* src = g_u_h + ((((size_t)f * 32 + yy) * 32 + xx) << 7) + c16 * 8;
        uint32_t dst = abase + r * 256 + ((c16 * 16) ^ ((r & 7) << 4));
        CP16(dst, src, ok);
    }
    CP_COMMIT();

#define ISSUE_WB(s, k) do { \
    const __half* wsrc = g_WBh + (((size_t)(k) * 4 + nb) << 14); \
    _Pragma("unroll") \
    for (int q = 0; q < 4; q++) { \
        int idx = q * 512 + tid; \
        CP16(wbase + (s) * 32768 + idx * 16, wsrc + idx * 8, true); \
    } \
} while (0)

    ISSUE_WB(0, 0); CP_COMMIT();
    ISSUE_WB(1, 1); CP_COMMIT();
    for (int k = 0; k < 9; k++) {
        if (k < 8) CP_WAIT1(); else CP_WAIT0();
        __syncthreads();
        if (k + 2 < 9) { ISSUE_WB((k + 2) % 3, k + 2); CP_COMMIT(); }
        COMPH(k % 3, k / 3, k % 3);
    }

    __half* base = (nb < 2) ? (__half*)g_Bus_hre : (__half*)g_Bus_him;
    int ch0 = (nb & 1) * 128 + wn * 32;
#pragma unroll
    for (int mt = 0; mt < 4; mt++) {
        int m1 = wm * 64 + mt * 16 + g8, m2 = m1 + 8;
        size_t pix1 = (((size_t)f * 32 + y0 + (m1 >> 5)) * 32 + (m1 & 31)) * 256;
        size_t pix2 = (((size_t)f * 32 + y0 + (m2 >> 5)) * 32 + (m2 & 31)) * 256;
#pragma unroll
        for (int nt = 0; nt < 4; nt++) {
            int ch = ch0 + nt * 8 + tig * 2;
            *(__half2*)(base + pix1 + ch) = __floats2half2_rn(acc[mt][nt][0], acc[mt][nt][1]);
            *(__half2*)(base + pix2 + ch) = __floats2half2_rn(acc[mt][nt][2], acc[mt][nt][3]);
        }
    }
    (void)dummy;
}

// ---------------- K2: scan (half2 Bus in, half xs out, f32 x_last) ---------
__global__ __launch_bounds__(256) void k_scan(const float* __restrict__ x0,
                                              float* __restrict__ out) {
    int t = blockIdx.x * 256 + threadIdx.x;
    int p0 = (2 * t) & 255;
    float ar0 = g_Are[p0],     ai0 = g_Aim[p0];
    float ar1 = g_Are[p0 + 1], ai1 = g_Aim[p0 + 1];
    float2 xv = ((const float2*)x0)[t];
    float xr0 = xv.x, xi0 = 0.f, xr1 = xv.y, xi1 = 0.f;
    size_t idx = (size_t)t;
#pragma unroll
    for (int l = 0; l < L_T; l++, idx += SP / 2) {
        float2 br = __half22float2(g_Bus_hre[idx]);
        float2 bi = __half22float2(g_Bus_him[idx]);
        float nr0 = fmaf(ar0, xr0, fmaf(-ai0, xi0, br.x));
        float ni0 = fmaf(ar0, xi0, fmaf( ai0, xr0, bi.x));
        float nr1 = fmaf(ar1, xr1, fmaf(-ai1, xi1, br.y));
        float ni1 = fmaf(ar1, xi1, fmaf( ai1, xr1, bi.y));
        xr0 = nr0; xi0 = ni0; xr1 = nr1; xi1 = ni1;
        ((__half2*)g_xh_re)[idx] = __floats2half2_rn(xr0, xr1);
        ((__half2*)g_xh_im)[idx] = __floats2half2_rn(xi0, xi1);
    }
    ((float4*)out)[t] = make_float4(xr0, xi0, xr1, xi1);
}

// ---------------- GEMM C: ys = 2Re(C (*) x), K-split re/im -----------------
// grid (slab4, f128, half2), 512 thr. 2 cb phases x 9 taps, halo reload between.
__global__ __launch_bounds__(512, 1) void k_gemmC(int dummy) {
    extern __shared__ __align__(16) char smem[];
    int tid = threadIdx.x, lane = tid & 31, wid = tid >> 5;
    int wm = wid >> 2, wn = wid & 3;
    int g8 = lane >> 2, tig = lane & 3;
    int lrow = lane & 15, lcol = lane & 16;
    int slab = blockIdx.x, f = blockIdx.y, half = blockIdx.z;
    int y0 = slab * 8;
    const __half* srcb = half ? g_xh_im : g_xh_re;
    uint32_t abase = (uint32_t)__cvta_generic_to_shared(smem);
    uint32_t wbase = abase + HALO_BYTES;

    float acc[4][4][4];
#pragma unroll
    for (int i = 0; i < 4; i++)
#pragma unroll
        for (int j = 0; j < 4; j++)
#pragma unroll
            for (int e = 0; e < 4; e++) acc[i][j][e] = 0.f;

#define ISSUE_HALO_C(cb) do { \
    for (int idx = tid; idx < 5440; idx += 512) { \
        int r = idx >> 4, c16 = idx & 15; \
        int hy = r / 34, hx = r - hy * 34; \
        int yy = y0 + hy - 1, xx = hx - 1; \
        bool ok = ((unsigned)yy < 32u) && ((unsigned)xx < 32u); \
        const __half* src = srcb + ((((size_t)f * 32 + yy) * 32 + xx) << 8) + (cb) * 128 + c16 * 8; \
        uint32_t dst = abase + r * 256 + ((c16 * 16) ^ ((r & 7) << 4)); \
        CP16(dst, src, ok); \
    } \
} while (0)

#define ISSUE_WC(s, c) do { \
    const __half* wsrc = g_WCh + (((size_t)half * 18 + (c)) << 14); \
    _Pragma("unroll") \
    for (int q = 0; q < 4; q++) { \
        int idx = q * 512 + tid; \
        CP16(wbase + (s) * 32768 + idx * 16, wsrc + idx * 8, true); \
    } \
} while (0)

    // ---- phase cb=0 ----
    ISSUE_HALO_C(0); CP_COMMIT();
    ISSUE_WC(0, 0); CP_COMMIT();
    ISSUE_WC(1, 1); CP_COMMIT();
    for (int k = 0; k < 9; k++) {
        if (k < 8) CP_WAIT1(); else CP_WAIT0();
        __syncthreads();
        if (k + 2 < 9) { ISSUE_WC((k + 2) % 3, k + 2); CP_COMMIT(); }
        COMPH(k % 3, k / 3, k % 3);
    }
    // ---- phase switch: drain reads of halo, reload for cb=1 ----
    __syncthreads();
    ISSUE_HALO_C(1); CP_COMMIT();
    ISSUE_WC(0, 9); CP_COMMIT();
    ISSUE_WC(1, 10); CP_COMMIT();
    for (int k = 0; k < 9; k++) {
        if (k < 8) CP_WAIT1(); else CP_WAIT0();
        __syncthreads();
        if (k + 2 < 9) { ISSUE_WC((k + 2) % 3, k + 11); CP_COMMIT(); }
        COMPH(k % 3, k / 3, k % 3);
    }

    float* ybase = half ? g_ys2 : g_ys;
#pragma unroll
    for (int mt = 0; mt < 4; mt++) {
        int m1 = wm * 64 + mt * 16 + g8, m2 = m1 + 8;
        size_t pix1 = (((size_t)f * 32 + y0 + (m1 >> 5)) * 32 + (m1 & 31)) * 128;
        size_t pix2 = (((size_t)f * 32 + y0 + (m2 >> 5)) * 32 + (m2 & 31)) * 128;
#pragma unroll
        for (int nt = 0; nt < 4; nt++) {
            int ch = wn * 32 + nt * 8 + tig * 2;
            *(float2*)(ybase + pix1 + ch) = make_float2(acc[mt][nt][0], acc[mt][nt][1]);
            *(float2*)(ybase + pix2 + ch) = make_float2(acc[mt][nt][2], acc[mt][nt][3]);
        }
    }
    (void)dummy;
}

// ---------------- K3b: depthwise D feedthrough (f32, coalesced) ------------
__global__ __launch_bounds__(128) void k_dw(const float* __restrict__ u_in,
                                            const float* __restrict__ Dk) {
    int f = blockIdx.x, y = blockIdx.y, u = threadIdx.x;
    float dk[9];
#pragma unroll
    for (int j = 0; j < 9; j++) dk[j] = Dk[j * U_ + u];
    float acc[W_];
#pragma unroll
    for (int x = 0; x < W_; x++) acc[x] = 0.f;
    for (int ky = 0; ky < 3; ky++) {
        int yi = y + ky - 1;
        if (yi < 0 || yi >= H_) continue;
        const float* row = u_in + ((size_t)(f * H_ + yi) * W_) * U_ + u;
        float v0 = 0.f, v1 = row[0];
#pragma unroll
        for (int x = 0; x < W_; x++) {
            float v2 = (x + 1 < W_) ? row[(x + 1) * U_] : 0.f;
            acc[x] = fmaf(v0, dk[ky * 3], fmaf(v1, dk[ky * 3 + 1], fmaf(v2, dk[ky * 3 + 2], acc[x])));
            v0 = v1; v1 = v2;
        }
    }
    size_t base = ((size_t)(f * H_ + y) * W_) * U_ + u;
#pragma unroll
    for (int x = 0; x < W_; x++) g_ys[base + (size_t)x * U_] += acc[x];
}

// ---------------- K4: GroupNorm(32) + tanh-GELU (sums ys + ys2) ------------
__global__ __launch_bounds__(256) void k_gn(const float* __restrict__ scale,
                                            const float* __restrict__ bias,
                                            float* __restrict__ out) {
    int f = blockIdx.x, g = blockIdx.y;
    size_t base = (size_t)f * (H_ * W_ * U_) + g * 4;

    float s = 0.f, s2 = 0.f;
    for (int j = threadIdx.x; j < H_ * W_ * 4; j += 256) {
        int yx = j >> 2, cl = j & 3;
        size_t idx = base + (size_t)yx * U_ + cl;
        float v = g_ys[idx] + g_ys2[idx];
        s += v; s2 += v * v;
    }
    __shared__ float rs[8], rs2[8];
    unsigned m = 0xffffffffu;
#pragma unroll
    for (int o = 16; o > 0; o >>= 1) {
        s  += __shfl_down_sync(m, s, o);
        s2 += __shfl_down_sync(m, s2, o);
    }
    if ((threadIdx.x & 31) == 0) { rs[threadIdx.x >> 5] = s; rs2[threadIdx.x >> 5] = s2; }
    __syncthreads();
    if (threadIdx.x == 0) {
        float ts = 0.f, ts2 = 0.f;
#pragma unroll
        for (int i = 0; i < 8; i++) { ts += rs[i]; ts2 += rs2[i]; }
        float mu  = ts * (1.f / 4096.f);
        float var = ts2 * (1.f / 4096.f) - mu * mu;
        rs[0]  = mu;
        rs2[0] = rsqrtf(var + EPS_GN);
    }
    __syncthreads();
    float mu = rs[0], rstd = rs2[0];

    float sc[4], bi[4];
#pragma unroll
    for (int c = 0; c < 4; c++) { sc[c] = scale[g * 4 + c]; bi[c] = bias[g * 4 + c]; }

    float* outy = out + (size_t)SP * 2;
    for (int j = threadIdx.x; j < H_ * W_ * 4; j += 256) {
        int yx = j >> 2, cl = j & 3;
        size_t idx = base + (size_t)yx * U_ + cl;
        float v = g_ys[idx] + g_ys2[idx];
        float h = (v - mu) * rstd * sc[cl] + bi[cl];
        float t = 0.7978845608028654f * (h + 0.044715f * h * h * h);
        outy[idx] = 0.5f * h * (1.f + tanhf(t));
    }
}

// ---------------- launch ----------------
extern "C" void kernel_launch(void* const* d_in, const int* in_sizes, int n_in,
                              void* d_out, int out_size) {
    const float* u_in  = (const float*)d_in[0];
    const float* x0    = (const float*)d_in[1];
    const float* Lre   = (const float*)d_in[2];
    const float* Lim   = (const float*)d_in[3];
    const float* B_ri  = (const float*)d_in[4];
    const float* C_ri  = (const float*)d_in[5];
    const float* lstep = (const float*)d_in[6];
    const float* Dk    = (const float*)d_in[7];
    const float* gsc   = (const float*)d_in[8];
    const float* gbi   = (const float*)d_in[9];
    float* out = (float*)d_out;
    (void)in_sizes; (void)n_in; (void)out_size;

    cudaFuncSetAttribute(k_gemmB, cudaFuncAttributeMaxDynamicSharedMemorySize, SMEM_GEMM);
    cudaFuncSetAttribute(k_gemmC, cudaFuncAttributeMaxDynamicSharedMemorySize, SMEM_GEMM);

    k_pre<<<(NB_W + NC_W + 255) / 256, 256>>>(Lre, Lim, lstep, B_ri, C_ri);
    k_uh<<<U_N / 4 / 256, 256>>>(u_in);
    k_gemmB<<<dim3(4, 4, FRAMES), 512, SMEM_GEMM>>>(0);
    k_scan<<<SP / 2 / 256, 256>>>(x0, out);
    k_gemmC<<<dim3(4, FRAMES, 2), 512, SMEM_GEMM>>>(0);
    k_dw<<<dim3(FRAMES, H_), 128>>>(u_in, Dk);
    k_gn<<<dim3(FRAMES, 32), 256>>>(gsc, gbi, out);
}